// round 6
// baseline (speedup 1.0000x reference)
#include <cuda_runtime.h>
#include <stdint.h>

#define NUM_CLASSES 10000
#define FEATURE_DIM 2048
#define BATCH 512
#define TPB 256
#define NTOT ((size_t)NUM_CLASSES * FEATURE_DIM)
#define COPY_GRID (148 * 8)
#define BM_WORDS ((NUM_CLASSES + 31) / 32)   // 313
// ALPHA = 0.5 exactly -> powers of two via ldexpf

__device__ int           g_lab[BATCH];      // decoded labels
__device__ unsigned int  g_bm[BM_WORDS];    // matched-class bitmap
__device__ unsigned char g_owner[BATCH];    // 1 if sample is first occurrence

// ---------------------------------------------------------------------------
// Init: zero loss, decode labels (int64 vs int32 probe), matched bitmap,
// first-occurrence ownership. One block, 512 threads.
// ---------------------------------------------------------------------------
__global__ void init_kernel(const int* __restrict__ labels_words,
                            float* __restrict__ loss_out) {
    __shared__ int s_not64;
    __shared__ int s_lab[BATCH];
    int tid = threadIdx.x;
    if (tid == 0) { s_not64 = 0; loss_out[0] = 0.0f; }
    for (int i = tid; i < BM_WORDS; i += BATCH) g_bm[i] = 0u;
    __syncthreads();
    int lo = labels_words[2 * tid];
    int hi = labels_words[2 * tid + 1];
    // int64 hypothesis: every odd 32-bit word 0, every even word a valid id.
    if (hi != 0 || lo < 0 || lo >= NUM_CLASSES) s_not64 = 1;   // benign race
    __syncthreads();
    int lab = s_not64 ? labels_words[tid] : lo;
    g_lab[tid] = lab;
    s_lab[tid] = lab;
    __syncthreads();
    atomicOr(&g_bm[lab >> 5], 1u << (lab & 31));
    int first = 1;
    for (int i = 0; i < tid; i++)
        if (s_lab[i] == lab) { first = 0; break; }
    g_owner[tid] = (unsigned char)first;
}

// ---------------------------------------------------------------------------
// Fused: blocks [0, BATCH) = owner blocks (closed-form EMA + loss for matched
// rows, overlapped with the copy); blocks [BATCH, BATCH+COPY_GRID) = row-
// blocked copy of all UNMATCHED rows. Disjoint rows -> race free.
// MODE 0: dst rows 16B-aligned.  MODE 1: dst base == 4 (mod 16): quads at
// drow+3+4j are aligned; carried .w via shfl_up (lane0: scalar load).
// MODE 2: scalar fallback.
// ---------------------------------------------------------------------------
template <int MODE>
__global__ void __launch_bounds__(TPB)
fused_kernel(const float* __restrict__ features,
             const float* __restrict__ centers,
             float* __restrict__ out_centers,
             float* __restrict__ loss_out) {
    const int tid = threadIdx.x;

    if (blockIdx.x < BATCH) {
        // ---------------- owner block ----------------
        const int b = blockIdx.x;
        if (!g_owner[b]) return;
        __shared__ int   s_match[BATCH];
        __shared__ float s_w[BATCH];
        __shared__ int   s_cnt;
        __shared__ float s_red[TPB / 32];
        const int l = g_lab[b];
        if (tid == 0) s_cnt = 0;
        __syncthreads();
        for (int j = tid; j < BATCH; j += TPB)
            if (g_lab[j] == l) s_match[atomicAdd(&s_cnt, 1)] = j;
        __syncthreads();
        const int k = s_cnt;
        if (tid == 0) {   // restore batch order, precompute weights
            for (int a = 1; a < k; a++) {
                int v = s_match[a], c = a - 1;
                while (c >= 0 && s_match[c] > v) { s_match[c + 1] = s_match[c]; c--; }
                s_match[c + 1] = v;
            }
            for (int r = 0; r < k; r++) s_w[r] = ldexpf(1.0f, -(k - r));
        }
        __syncthreads();

        const float* crow = centers     + (size_t)l * FEATURE_DIM;
        float*       orow = out_centers + (size_t)l * FEATURE_DIM;
        const float  decay = ldexpf(1.0f, -k);
        float acc = 0.0f;
        #pragma unroll
        for (int s = 0; s < FEATURE_DIM / TPB; s++) {
            int c = tid + s * TPB;
            float cv = __ldg(crow + c);
            float nv = cv * decay;
            for (int r = 0; r < k; r++) {
                float f = __ldg(features + (size_t)s_match[r] * FEATURE_DIM + c);
                nv = fmaf(s_w[r], f, nv);
                float d = f - cv;                 // loss vs ORIGINAL center
                acc = fmaf(d, d, acc);
            }
            orow[c] = nv;
        }
        #pragma unroll
        for (int o = 16; o; o >>= 1) acc += __shfl_xor_sync(0xffffffffu, acc, o);
        if ((tid & 31) == 0) s_red[tid >> 5] = acc;
        __syncthreads();
        if (tid < TPB / 32) {
            acc = s_red[tid];
            #pragma unroll
            for (int o = (TPB / 64); o; o >>= 1)
                acc += __shfl_xor_sync((1u << (TPB / 32)) - 1u, acc, o);
            if (tid == 0)
                atomicAdd(loss_out, acc * (1.0f / ((float)BATCH * (float)FEATURE_DIM)));
        }
        return;
    }

    // ---------------- copy block ----------------
    __shared__ unsigned int s_bm[BM_WORDS];
    for (int i = tid; i < BM_WORDS; i += TPB)     // FIX: BM_WORDS > TPB
        s_bm[i] = g_bm[i];
    __syncthreads();

    const int cid  = blockIdx.x - BATCH;
    const int lane = tid & 31;

    for (int r = cid; r < NUM_CLASSES; r += COPY_GRID) {
        if ((s_bm[r >> 5] >> (r & 31)) & 1u) continue;   // owner handles it
        const float* srow = centers     + (size_t)r * FEATURE_DIM;
        float*       drow = out_centers + (size_t)r * FEATURE_DIM;

        if (MODE == 0) {
            const float4* s4 = (const float4*)srow;
            float4*       d4 = (float4*)drow;
            #pragma unroll
            for (int s = 0; s < (FEATURE_DIM / 4) / TPB; s++) {
                int j = tid + s * TPB;
                d4[j] = __ldg(s4 + j);
            }
        } else if (MODE == 1) {
            // drow == 4 (mod 16): quads [3+4j .. 6+4j], j in [0, 511).
            // Edge scalars: 0,1,2,2047.
            if (tid < 3)  drow[tid] = __ldg(srow + tid);
            if (tid == 3) drow[FEATURE_DIM - 1] = __ldg(srow + FEATURE_DIM - 1);
            #pragma unroll
            for (int s = 0; s < 2; s++) {
                int  j   = tid + s * TPB;
                bool act = j < (FEATURE_DIM / 4) - 1;        // j < 511
                int  jc  = act ? j : (FEATURE_DIM / 4) - 2;  // safe clamp
                float4 q = __ldg((const float4*)srow + jc + 1);
                float  w = __shfl_up_sync(0xffffffffu, q.w, 1);
                if (lane == 0) w = __ldg(srow + 4 * jc + 3);
                if (act)
                    *(float4*)(drow + 3 + 4 * j) = make_float4(w, q.x, q.y, q.z);
            }
        } else {
            #pragma unroll
            for (int s = 0; s < FEATURE_DIM / TPB; s++) {
                int c = tid + s * TPB;
                drow[c] = __ldg(srow + c);
            }
        }
    }
}

extern "C" void kernel_launch(void* const* d_in, const int* in_sizes, int n_in,
                              void* d_out, int out_size) {
    const float* features = (const float*)d_in[0];
    const int*   labels_w = (const int*)d_in[1];
    const float* centers  = (const float*)d_in[2];

    float* out = (float*)d_out;
    float* out_centers = out + ((size_t)out_size - NTOT);

    init_kernel<<<1, BATCH>>>(labels_w, out);

    const int GRID = BATCH + COPY_GRID;
    uintptr_t a = (uintptr_t)out_centers;
    if ((a & 15) == 0)
        fused_kernel<0><<<GRID, TPB>>>(features, centers, out_centers, out);
    else if ((a & 15) == 4)
        fused_kernel<1><<<GRID, TPB>>>(features, centers, out_centers, out);
    else
        fused_kernel<2><<<GRID, TPB>>>(features, centers, out_centers, out);
}

// round 8
// speedup vs baseline: 1.4243x; 1.4243x over previous
#include <cuda_runtime.h>
#include <stdint.h>

#define NUM_CLASSES 10000
#define FEATURE_DIM 2048
#define BATCH 512
#define TPB 256
#define NTOT ((size_t)NUM_CLASSES * FEATURE_DIM)
#define COPY_GRID (148 * 8)
#define BM_WORDS ((NUM_CLASSES + 31) / 32)   // 313
// ALPHA = 0.5 exactly -> powers of two via ldexpf

__device__ int           g_lab[BATCH];      // decoded labels
__device__ unsigned int  g_bm[BM_WORDS];    // matched-class bitmap
__device__ unsigned char g_owner[BATCH];    // 1 if sample owns its label's row

// ---------------------------------------------------------------------------
// Init: zero loss, decode labels (int64 vs int32 probe), matched bitmap,
// ownership. One block, 512 threads, O(1) per thread:
// atomicOr returns the pre-update word -> exactly one thread per distinct
// label sees its bit clear; that thread owns the label. (The owner block
// re-collects all matched indices in batch order itself, so WHICH sample
// owns the label is irrelevant — only uniqueness matters.)
// ---------------------------------------------------------------------------
__global__ void init_kernel(const int* __restrict__ labels_words,
                            float* __restrict__ loss_out) {
    __shared__ int s_not64;
    int tid = threadIdx.x;
    if (tid == 0) { s_not64 = 0; loss_out[0] = 0.0f; }
    for (int i = tid; i < BM_WORDS; i += BATCH) g_bm[i] = 0u;
    __syncthreads();
    int lo = labels_words[2 * tid];
    int hi = labels_words[2 * tid + 1];
    // int64 hypothesis: every odd 32-bit word 0, every even word a valid id.
    if (hi != 0 || lo < 0 || lo >= NUM_CLASSES) s_not64 = 1;   // benign race
    __syncthreads();
    int lab = s_not64 ? labels_words[tid] : lo;
    g_lab[tid] = lab;
    unsigned int bit = 1u << (lab & 31);
    unsigned int old = atomicOr(&g_bm[lab >> 5], bit);
    g_owner[tid] = (unsigned char)((old & bit) == 0u);
}

// ---------------------------------------------------------------------------
// Fused: blocks [0, BATCH) = owner blocks (closed-form EMA + loss for matched
// rows, overlapped with the copy); blocks [BATCH, BATCH+COPY_GRID) = row-
// blocked copy of all UNMATCHED rows. Disjoint rows -> race free.
// MODE 0: dst rows 16B-aligned.  MODE 1: dst base == 4 (mod 16): quads at
// drow+3+4j are aligned; carried .w via shfl_up (lane0: scalar load).
// MODE 2: scalar fallback.
// ---------------------------------------------------------------------------
template <int MODE>
__global__ void __launch_bounds__(TPB)
fused_kernel(const float* __restrict__ features,
             const float* __restrict__ centers,
             float* __restrict__ out_centers,
             float* __restrict__ loss_out) {
    const int tid = threadIdx.x;

    if (blockIdx.x < BATCH) {
        // ---------------- owner block ----------------
        const int b = blockIdx.x;
        if (!g_owner[b]) return;
        __shared__ int   s_match[BATCH];
        __shared__ float s_w[BATCH];
        __shared__ int   s_cnt;
        __shared__ float s_red[TPB / 32];
        const int l = g_lab[b];
        if (tid == 0) s_cnt = 0;
        __syncthreads();
        for (int j = tid; j < BATCH; j += TPB)
            if (g_lab[j] == l) s_match[atomicAdd(&s_cnt, 1)] = j;
        __syncthreads();
        const int k = s_cnt;
        if (tid == 0) {   // restore batch order, precompute weights
            for (int a = 1; a < k; a++) {
                int v = s_match[a], c = a - 1;
                while (c >= 0 && s_match[c] > v) { s_match[c + 1] = s_match[c]; c--; }
                s_match[c + 1] = v;
            }
            for (int r = 0; r < k; r++) s_w[r] = ldexpf(1.0f, -(k - r));
        }
        __syncthreads();

        const float* crow = centers     + (size_t)l * FEATURE_DIM;
        float*       orow = out_centers + (size_t)l * FEATURE_DIM;
        const float  decay = ldexpf(1.0f, -k);
        float acc = 0.0f;
        #pragma unroll
        for (int s = 0; s < FEATURE_DIM / TPB; s++) {
            int c = tid + s * TPB;
            float cv = __ldg(crow + c);
            float nv = cv * decay;
            for (int r = 0; r < k; r++) {
                float f = __ldg(features + (size_t)s_match[r] * FEATURE_DIM + c);
                nv = fmaf(s_w[r], f, nv);
                float d = f - cv;                 // loss vs ORIGINAL center
                acc = fmaf(d, d, acc);
            }
            orow[c] = nv;
        }
        #pragma unroll
        for (int o = 16; o; o >>= 1) acc += __shfl_xor_sync(0xffffffffu, acc, o);
        if ((tid & 31) == 0) s_red[tid >> 5] = acc;
        __syncthreads();
        if (tid < TPB / 32) {
            acc = s_red[tid];
            #pragma unroll
            for (int o = (TPB / 64); o; o >>= 1)
                acc += __shfl_xor_sync((1u << (TPB / 32)) - 1u, acc, o);
            if (tid == 0)
                atomicAdd(loss_out, acc * (1.0f / ((float)BATCH * (float)FEATURE_DIM)));
        }
        return;
    }

    // ---------------- copy block ----------------
    __shared__ unsigned int s_bm[BM_WORDS];
    for (int i = tid; i < BM_WORDS; i += TPB)
        s_bm[i] = g_bm[i];
    __syncthreads();

    const int cid  = blockIdx.x - BATCH;
    const int lane = tid & 31;

    for (int r = cid; r < NUM_CLASSES; r += COPY_GRID) {
        if ((s_bm[r >> 5] >> (r & 31)) & 1u) continue;   // owner handles it
        const float* srow = centers     + (size_t)r * FEATURE_DIM;
        float*       drow = out_centers + (size_t)r * FEATURE_DIM;

        if (MODE == 0) {
            const float4* s4 = (const float4*)srow;
            float4*       d4 = (float4*)drow;
            #pragma unroll
            for (int s = 0; s < (FEATURE_DIM / 4) / TPB; s++) {
                int j = tid + s * TPB;
                d4[j] = __ldg(s4 + j);
            }
        } else if (MODE == 1) {
            // drow == 4 (mod 16): quads [3+4j .. 6+4j], j in [0, 511).
            // Edge scalars: 0,1,2,2047.
            if (tid < 3)  drow[tid] = __ldg(srow + tid);
            if (tid == 3) drow[FEATURE_DIM - 1] = __ldg(srow + FEATURE_DIM - 1);
            #pragma unroll
            for (int s = 0; s < 2; s++) {
                int  j   = tid + s * TPB;
                bool act = j < (FEATURE_DIM / 4) - 1;        // j < 511
                int  jc  = act ? j : (FEATURE_DIM / 4) - 2;  // safe clamp
                float4 q = __ldg((const float4*)srow + jc + 1);
                float  w = __shfl_up_sync(0xffffffffu, q.w, 1);
                if (lane == 0) w = __ldg(srow + 4 * jc + 3);
                if (act)
                    *(float4*)(drow + 3 + 4 * j) = make_float4(w, q.x, q.y, q.z);
            }
        } else {
            #pragma unroll
            for (int s = 0; s < FEATURE_DIM / TPB; s++) {
                int c = tid + s * TPB;
                drow[c] = __ldg(srow + c);
            }
        }
    }
}

extern "C" void kernel_launch(void* const* d_in, const int* in_sizes, int n_in,
                              void* d_out, int out_size) {
    const float* features = (const float*)d_in[0];
    const int*   labels_w = (const int*)d_in[1];
    const float* centers  = (const float*)d_in[2];

    float* out = (float*)d_out;
    float* out_centers = out + ((size_t)out_size - NTOT);

    init_kernel<<<1, BATCH>>>(labels_w, out);

    const int GRID = BATCH + COPY_GRID;
    uintptr_t a = (uintptr_t)out_centers;
    if ((a & 15) == 0)
        fused_kernel<0><<<GRID, TPB>>>(features, centers, out_centers, out);
    else if ((a & 15) == 4)
        fused_kernel<1><<<GRID, TPB>>>(features, centers, out_centers, out);
    else
        fused_kernel<2><<<GRID, TPB>>>(features, centers, out_centers, out);
}